// round 8
// baseline (speedup 1.0000x reference)
#include <cuda_runtime.h>
#include <cuda_fp16.h>
#include <cstdint>
#include <math.h>

#define BB 4
#define SSEQ 2048
#define DIMX 512
#define HEADS 8
#define DHEAD 64
#define INNER 512
#define NROWS (BB * SSEQ)   // 8192
#define LOSCALE 2048.0f
#define INV_LOSCALE (1.0f / 2048.0f)

// ---------------- device scratch -------------------------------------------
__device__ __half g_xh[NROWS * DIMX],      g_xl[NROWS * DIMX];     // xl pre-scaled by 2048
__device__ __half g_wqh[3 * INNER * DIMX], g_wql[3 * INNER * DIMX]; // wql pre-scaled
__device__ __half g_woh[DIMX * INNER];
__device__ __half g_q[NROWS * INNER];   // [bh][s][64]
__device__ __half g_k[NROWS * INNER];
__device__ __half g_v[NROWS * INNER];
__device__ __half g_a[NROWS * INNER];   // [b*s][512]

// ---------------- helpers ---------------------------------------------------
__device__ __forceinline__ uint32_t smem_u32(const void* p) {
    uint32_t a;
    asm("{ .reg .u64 t; cvta.to.shared.u64 t, %1; cvt.u32.u64 %0, t; }" : "=r"(a) : "l"(p));
    return a;
}
__device__ __forceinline__ void ldsm4(uint32_t& r0, uint32_t& r1, uint32_t& r2,
                                      uint32_t& r3, uint32_t addr) {
    asm volatile("ldmatrix.sync.aligned.m8n8.x4.shared.b16 {%0,%1,%2,%3}, [%4];"
                 : "=r"(r0), "=r"(r1), "=r"(r2), "=r"(r3) : "r"(addr));
}
__device__ __forceinline__ void ldsm4t(uint32_t& r0, uint32_t& r1, uint32_t& r2,
                                       uint32_t& r3, uint32_t addr) {
    asm volatile("ldmatrix.sync.aligned.m8n8.x4.trans.shared.b16 {%0,%1,%2,%3}, [%4];"
                 : "=r"(r0), "=r"(r1), "=r"(r2), "=r"(r3) : "r"(addr));
}
// fp32-accumulate HMMA
__device__ __forceinline__ void mma_f16(float* c, const uint32_t a[4],
                                        uint32_t b0, uint32_t b1) {
    asm volatile(
        "mma.sync.aligned.m16n8k16.row.col.f32.f16.f16.f32 "
        "{%0,%1,%2,%3}, {%4,%5,%6,%7}, {%8,%9}, {%0,%1,%2,%3};"
        : "+f"(c[0]), "+f"(c[1]), "+f"(c[2]), "+f"(c[3])
        : "r"(a[0]), "r"(a[1]), "r"(a[2]), "r"(a[3]), "r"(b0), "r"(b1));
}
// fp16-accumulate HMMA (2x rate hypothesis)
__device__ __forceinline__ void mma_f16h(uint32_t* c, const uint32_t a[4],
                                         uint32_t b0, uint32_t b1) {
    asm volatile(
        "mma.sync.aligned.m16n8k16.row.col.f16.f16.f16.f16 "
        "{%0,%1}, {%2,%3,%4,%5}, {%6,%7}, {%0,%1};"
        : "+r"(c[0]), "+r"(c[1])
        : "r"(a[0]), "r"(a[1]), "r"(a[2]), "r"(a[3]), "r"(b0), "r"(b1));
}
__device__ __forceinline__ void cp16(uint32_t dst, const void* src) {
    asm volatile("cp.async.cg.shared.global [%0], [%1], 16;" :: "r"(dst), "l"(src));
}
#define CP_COMMIT() asm volatile("cp.async.commit_group;" ::: "memory")
#define CP_WAIT1()  asm volatile("cp.async.wait_group 1;" ::: "memory")
#define CP_WAIT2()  asm volatile("cp.async.wait_group 2;" ::: "memory")

__device__ __forceinline__ uint32_t pkh(float a, float b) {   // a in low half
    __half2 x = __floats2half2_rn(a, b);
    return *reinterpret_cast<uint32_t*>(&x);
}
__device__ __forceinline__ float2 uph(uint32_t u) {
    return __half22float2(*reinterpret_cast<__half2*>(&u));
}
// 16B-chunk swizzle within 128B rows (conflict-free ldmatrix)
__device__ __forceinline__ uint32_t swz(int r, int c) {
    return (uint32_t)r * 128u + (uint32_t)((c ^ (r & 7)) & 7) * 16u;
}

// ---------------- convert kernels (fp16 hi + scaled lo) ----------------------
__global__ void k_split_h(const float* __restrict__ in, __half* __restrict__ hi,
                          __half* __restrict__ lo, int n) {
    int i = blockIdx.x * blockDim.x + threadIdx.x;
    if (i < n) {
        float f = in[i];
        __half h = __float2half_rn(f);
        hi[i] = h;
        lo[i] = __float2half_rn((f - __half2float(h)) * LOSCALE);
    }
}
template <bool LO>
__global__ void k_splitT_h(const float* __restrict__ in, __half* __restrict__ hi,
                           __half* __restrict__ lo, int K, int N) {
    int i = blockIdx.x * blockDim.x + threadIdx.x;
    if (i < K * N) {
        int n = i / K, k = i % K;
        float f = in[(size_t)k * N + n];
        __half h = __float2half_rn(f);
        hi[i] = h;
        if (LO) lo[i] = __float2half_rn((f - __half2float(h)) * LOSCALE);
    }
}

// ---------------- GEMM: hi fp32-acc + lo-terms fp16-acc, 512 threads ---------
// tile 128x128, warp grid 4x4, warp tile 32x32.
// MODE 0: q/k tiles (n0<1024) 3 terms; V tiles 1 term. -> q/k/v fp16 [bh][s][d]
// MODE 1: 1 term, fp32 + bias.
template <int MODE>
__global__ void __launch_bounds__(512, 1)
gemm_mma(const __half* __restrict__ Ah, const __half* __restrict__ Al,
         const __half* __restrict__ Bh, const __half* __restrict__ Bl,
         int Kd,
         __half* __restrict__ q, __half* __restrict__ k, __half* __restrict__ v,
         const float* __restrict__ bias, float* __restrict__ outp) {
    extern __shared__ char smc[];
    const uint32_t sb = smem_u32(smc);
    const int tid = threadIdx.x, w = tid >> 5, lane = tid & 31;
    const int m0 = blockIdx.y * 128, n0 = blockIdx.x * 128;
    const int wm = w & 3, wn = w >> 2;
    const uint32_t STG = 65536;
    const bool full = (MODE == 0 && n0 < 1024);

    float acc[2][4][4] = {};
    uint32_t accL[2][4][2] = {};   // fp16 accumulator for the 2 lo cross-terms

    auto issue = [&](int kc, int stg) {
        uint32_t base = sb + (uint32_t)stg * STG;
#pragma unroll
        for (int i = tid; i < 1024; i += 512) {
            int r = i >> 3, c = i & 7;
            uint32_t off = swz(r, c);
            size_t ga = (size_t)(m0 + r) * Kd + kc + c * 8;
            size_t gb = (size_t)(n0 + r) * Kd + kc + c * 8;
            cp16(base + off,          Ah + ga);
            cp16(base + 32768 + off,  Bh + gb);
            if (full) {
                cp16(base + 16384 + off, Al + ga);
                cp16(base + 49152 + off, Bl + gb);
            }
        }
    };

    const int nch = Kd / 64;
    issue(0, 0); CP_COMMIT();

    for (int kc = 0; kc < nch; kc++) {
        if (kc + 1 < nch) issue((kc + 1) * 64, (kc + 1) & 1);
        CP_COMMIT();
        CP_WAIT1();
        __syncthreads();

        const uint32_t As = sb + (uint32_t)(kc & 1) * STG;
        const uint32_t Bs = As + 32768;
#pragma unroll
        for (int ks = 0; ks < 4; ks++) {
            // load all fragments once, reuse across terms
            uint32_t ah[2][4], al[2][4];
#pragma unroll
            for (int mt = 0; mt < 2; mt++) {
                int rr = 32 * wm + 16 * mt + (lane & 7) + ((lane >> 3) & 1) * 8;
                int cc = 2 * ks + (lane >> 4);
                ldsm4(ah[mt][0], ah[mt][1], ah[mt][2], ah[mt][3], As + swz(rr, cc));
                if (full)
                    ldsm4(al[mt][0], al[mt][1], al[mt][2], al[mt][3],
                          As + 16384 + swz(rr, cc));
            }
#pragma unroll
            for (int ntp = 0; ntp < 2; ntp++) {
                int rr = 32 * wn + 16 * ntp + (lane & 7) + ((lane >> 4) ? 8 : 0);
                int cc = 2 * ks + ((lane >> 3) & 1);
                uint32_t bh0, bh1, bh2, bh3;
                ldsm4(bh0, bh1, bh2, bh3, Bs + swz(rr, cc));
#pragma unroll
                for (int mt = 0; mt < 2; mt++) {
                    mma_f16(acc[mt][2 * ntp],     ah[mt], bh0, bh1);
                    mma_f16(acc[mt][2 * ntp + 1], ah[mt], bh2, bh3);
                }
                if (full) {
                    uint32_t bl0, bl1, bl2, bl3;
                    ldsm4(bl0, bl1, bl2, bl3, Bs + 16384 + swz(rr, cc));
#pragma unroll
                    for (int mt = 0; mt < 2; mt++) {
                        mma_f16h(accL[mt][2 * ntp],     ah[mt], bl0, bl1);   // xh*wl'
                        mma_f16h(accL[mt][2 * ntp + 1], ah[mt], bl2, bl3);
                        mma_f16h(accL[mt][2 * ntp],     al[mt], bh0, bh1);   // xl'*wh
                        mma_f16h(accL[mt][2 * ntp + 1], al[mt], bh2, bh3);
                    }
                }
            }
        }
        __syncthreads();
    }

    // epilogue
#pragma unroll
    for (int mt = 0; mt < 2; mt++) {
#pragma unroll
        for (int i = 0; i < 2; i++) {
            const int gm = m0 + 32 * wm + 16 * mt + (lane >> 2) + i * 8;
#pragma unroll
            for (int nt = 0; nt < 4; nt++) {
                const int gn = n0 + 32 * wn + 8 * nt + 2 * (lane & 3);
                float v0 = acc[mt][nt][2 * i], v1 = acc[mt][nt][2 * i + 1];
                if (full) {
                    float2 lo = uph(accL[mt][nt][i]);
                    v0 += lo.x * INV_LOSCALE;
                    v1 += lo.y * INV_LOSCALE;
                }
                if (MODE == 0) {
                    const int seg = gn >> 9, nn = gn & 511;
                    const int h = nn >> 6, d = nn & 63;
                    const int bI = gm >> 11, s = gm & 2047;
                    size_t idx = ((size_t)((bI * 8 + h) * 2048 + s)) * 64 + d;
                    __half* dst = (seg == 0) ? q : (seg == 1) ? k : v;
                    *reinterpret_cast<uint32_t*>(dst + idx) = pkh(v0, v1);
                } else {
                    float2 o = make_float2(v0 + bias[gn], v1 + bias[gn + 1]);
                    *reinterpret_cast<float2*>(outp + (size_t)gm * 512 + gn) = o;
                }
            }
        }
    }
}

// ---------------- attention: QK fp16-acc, PV fp32-acc ------------------------
__global__ void __launch_bounds__(256, 1)
attn_mma(const __half* __restrict__ qg, const __half* __restrict__ kg,
         const __half* __restrict__ vg, const float* __restrict__ log_temp,
         __half* __restrict__ aout) {
    extern __shared__ char smc[];
    const uint32_t sb = smem_u32(smc);
    const int tid = threadIdx.x, w = tid >> 5, lane = tid & 31;
    const int q0 = blockIdx.x * 128;
    const int bh = blockIdx.y, b = bh >> 3, h = bh & 7;
    const uint32_t KO = 0, VO = 16384, STG = 32768, QO = 98304;

    const float scale = __expf(*log_temp);
    const size_t bho = (size_t)bh * 2048 * 64;

    // Q -> smem
#pragma unroll
    for (int i = tid; i < 1024; i += 256) {
        int r = i >> 3, c = i & 7;
        *reinterpret_cast<uint4*>(smc + QO + swz(r, c)) =
            *reinterpret_cast<const uint4*>(qg + bho + (size_t)(q0 + r) * 64 + c * 8);
    }

    auto issue = [&](int t, int stg) {
        const size_t o = bho + (size_t)t * 128 * 64;
        uint32_t base = sb + (uint32_t)stg * STG;
#pragma unroll
        for (int i = tid; i < 1024; i += 256) {
            int r = i >> 3, c = i & 7;
            uint32_t off = swz(r, c);
            size_t g = o + (size_t)r * 64 + c * 8;
            cp16(base + KO + off, kg + g);
            cp16(base + VO + off, vg + g);
        }
    };
    issue(0, 0); CP_COMMIT();
    issue(1, 1); CP_COMMIT();
    __syncthreads();   // Q visible

    uint32_t aq[4][4];
    {
        int rr = 16 * w + (lane & 7) + ((lane >> 3) & 1) * 8;
#pragma unroll
        for (int ks = 0; ks < 4; ks++) {
            int cc = 2 * ks + (lane >> 4);
            ldsm4(aq[ks][0], aq[ks][1], aq[ks][2], aq[ks][3], sb + QO + swz(rr, cc));
        }
    }

    float O[8][4] = {};
    float l0 = 0.f, l1 = 0.f;
    const int rg = 16 * w + (lane >> 2);
    const int qi0 = q0 + rg, qi1 = qi0 + 8;

    for (int t = 0; t < 16; t++) {
        if (t + 2 < 16) {
            int nt_ = t + 2;
            int s3 = nt_ - (nt_ >= 3 ? 3 : 0) - (nt_ >= 6 ? 3 : 0) - (nt_ >= 9 ? 3 : 0)
                   - (nt_ >= 12 ? 3 : 0) - (nt_ >= 15 ? 3 : 0);
            issue(nt_, s3);
        }
        CP_COMMIT();
        CP_WAIT2();
        __syncthreads();

        int ts = t - (t >= 3 ? 3 : 0) - (t >= 6 ? 3 : 0) - (t >= 9 ? 3 : 0)
               - (t >= 12 ? 3 : 0) - (t >= 15 ? 3 : 0);
        const uint32_t stgb = sb + (uint32_t)ts * STG;
        const uint32_t Ks = stgb + KO, Vs = stgb + VO;

        // S = Q @ K^T  (fp16 accumulate: 2x rate)
        uint32_t Sh[16][2];
#pragma unroll
        for (int nt = 0; nt < 16; nt++) { Sh[nt][0] = 0u; Sh[nt][1] = 0u; }
#pragma unroll
        for (int ks = 0; ks < 4; ks++) {
#pragma unroll
            for (int ntp = 0; ntp < 8; ntp++) {
                uint32_t b0, b1, b2, b3;
                int rr = 16 * ntp + (lane & 7) + ((lane >> 4) ? 8 : 0);
                int cc = 2 * ks + ((lane >> 3) & 1);
                ldsm4(b0, b1, b2, b3, Ks + swz(rr, cc));
                mma_f16h(Sh[2 * ntp],     aq[ks], b0, b1);
                mma_f16h(Sh[2 * ntp + 1], aq[ks], b2, b3);
            }
        }

        // exp + diag mask, pack P to fp16
        const int j00 = t * 128 + 2 * (lane & 3);
        uint32_t ep[16][2];
#pragma unroll
        for (int nt = 0; nt < 16; nt++) {
            int jc = j00 + 8 * nt;
            float2 s01 = uph(Sh[nt][0]);   // row qi0, cols jc, jc+1
            float2 s23 = uph(Sh[nt][1]);   // row qi1
            float e0 = (jc     == qi0) ? 0.f : __expf(s01.x * scale);
            float e1 = (jc + 1 == qi0) ? 0.f : __expf(s01.y * scale);
            float e2 = (jc     == qi1) ? 0.f : __expf(s23.x * scale);
            float e3 = (jc + 1 == qi1) ? 0.f : __expf(s23.y * scale);
            l0 += e0 + e1;
            l1 += e2 + e3;
            ep[nt][0] = pkh(e0, e1);
            ep[nt][1] = pkh(e2, e3);
        }

        // O += P @ V  (fp32 accumulate — long chain, must stay fp32)
#pragma unroll
        for (int ks = 0; ks < 8; ks++) {
            uint32_t ap[4] = { ep[2 * ks][0], ep[2 * ks][1],
                               ep[2 * ks + 1][0], ep[2 * ks + 1][1] };
#pragma unroll
            for (int ntp = 0; ntp < 4; ntp++) {
                uint32_t b0, b1, b2, b3;
                int rr = 16 * ks + (lane & 7) + ((lane >> 3) & 1) * 8;
                int cc = 2 * ntp + (lane >> 4);
                ldsm4t(b0, b1, b2, b3, Vs + swz(rr, cc));
                mma_f16(O[2 * ntp],     ap, b0, b1);
                mma_f16(O[2 * ntp + 1], ap, b2, b3);
            }
        }
        __syncthreads();
    }

    l0 += __shfl_xor_sync(0xffffffffu, l0, 1);
    l0 += __shfl_xor_sync(0xffffffffu, l0, 2);
    l1 += __shfl_xor_sync(0xffffffffu, l1, 1);
    l1 += __shfl_xor_sync(0xffffffffu, l1, 2);
    const float inv0 = 1.f / l0, inv1 = 1.f / l1;

#pragma unroll
    for (int i = 0; i < 2; i++) {
        const float inv = i ? inv1 : inv0;
        const size_t gm = (size_t)(b * 2048 + q0 + rg + i * 8);
#pragma unroll
        for (int nt = 0; nt < 8; nt++) {
            const int d = 8 * nt + 2 * (lane & 3);
            size_t idx = gm * INNER + h * DHEAD + d;
            *reinterpret_cast<uint32_t*>(aout + idx) =
                pkh(O[nt][2 * i] * inv, O[nt][2 * i + 1] * inv);
        }
    }
}

// ---------------- launch -----------------------------------------------------
extern "C" void kernel_launch(void* const* d_in, const int* in_sizes, int n_in,
                              void* d_out, int out_size) {
    const float* x        = (const float*)d_in[0];
    const float* W_qkv    = (const float*)d_in[1];
    const float* log_temp = (const float*)d_in[2];
    const float* W_out    = (const float*)d_in[3];
    const float* b_out    = (const float*)d_in[4];
    float* out = (float*)d_out;

    __half *xh, *xl, *wqh, *wql, *woh, *q, *k, *v, *a;
    cudaGetSymbolAddress((void**)&xh, g_xh);   cudaGetSymbolAddress((void**)&xl, g_xl);
    cudaGetSymbolAddress((void**)&wqh, g_wqh); cudaGetSymbolAddress((void**)&wql, g_wql);
    cudaGetSymbolAddress((void**)&woh, g_woh);
    cudaGetSymbolAddress((void**)&q, g_q);
    cudaGetSymbolAddress((void**)&k, g_k);
    cudaGetSymbolAddress((void**)&v, g_v);
    cudaGetSymbolAddress((void**)&a, g_a);

    const int GSM = 131072;
    const int ASM = 114688;
    cudaFuncSetAttribute(gemm_mma<0>, cudaFuncAttributeMaxDynamicSharedMemorySize, GSM);
    cudaFuncSetAttribute(gemm_mma<1>, cudaFuncAttributeMaxDynamicSharedMemorySize, GSM);
    cudaFuncSetAttribute(attn_mma,    cudaFuncAttributeMaxDynamicSharedMemorySize, ASM);

    k_split_h<<<(NROWS * DIMX + 255) / 256, 256>>>(x, xh, xl, NROWS * DIMX);
    k_splitT_h<true><<<(DIMX * 3 * INNER + 255) / 256, 256>>>(W_qkv, wqh, wql,
                                                              DIMX, 3 * INNER);
    k_splitT_h<false><<<(INNER * DIMX + 255) / 256, 256>>>(W_out, woh, nullptr,
                                                           INNER, DIMX);

    // 1) QKV projection: hi fp32-acc + scaled lo-terms fp16-acc
    gemm_mma<0><<<dim3(12, 64), 512, GSM>>>(xh, xl, wqh, wql, DIMX,
                                            q, k, v, nullptr, nullptr);
    // 2) attention: QK fp16-acc, PV fp32-acc
    attn_mma<<<dim3(SSEQ / 128, BB * HEADS), 256, ASM>>>(q, k, v, log_temp, a);
    // 3) output projection, 1-term + bias -> fp32
    gemm_mma<1><<<dim3(4, 64), 512, GSM>>>(a, a, woh, woh, INNER,
                                           nullptr, nullptr, nullptr, b_out, out);
}